// round 11
// baseline (speedup 1.0000x reference)
#include <cuda_runtime.h>
#include <cuda_fp16.h>
#include <cstdint>

#define EPS 1e-5f

__device__ __forceinline__ float tanh_fast(float x) {
    float y; asm("tanh.approx.f32 %0,%1;" : "=f"(y) : "f"(x)); return y;
}
__device__ __forceinline__ unsigned tanh2(unsigned v) {
    unsigned y; asm("tanh.approx.f16x2 %0,%1;" : "=r"(y) : "r"(v)); return y;
}
__device__ __forceinline__ unsigned packh2(float a, float b) {
    __half2 h = __floats2half2_rn(a, b);
    return *reinterpret_cast<unsigned*>(&h);
}

__device__ __forceinline__ void mma16(float* d,
                                      unsigned a0, unsigned a1, unsigned a2, unsigned a3,
                                      unsigned b0, unsigned b1) {
    asm volatile(
        "mma.sync.aligned.m16n8k16.row.col.f32.f16.f16.f32 "
        "{%0,%1,%2,%3},{%4,%5,%6,%7},{%8,%9},{%0,%1,%2,%3};"
        : "+f"(d[0]), "+f"(d[1]), "+f"(d[2]), "+f"(d[3])
        : "r"(a0), "r"(a1), "r"(a2), "r"(a3), "r"(b0), "r"(b1));
}

__device__ __forceinline__ void ldsm4(unsigned& r0, unsigned& r1, unsigned& r2, unsigned& r3,
                                      unsigned addr) {
    asm volatile("ldmatrix.sync.aligned.m8n8.x4.shared.b16 {%0,%1,%2,%3},[%4];"
                 : "=r"(r0), "=r"(r1), "=r"(r2), "=r"(r3) : "r"(addr));
}

// hb row stride: 72 halfs = 36 u32 words
#define HSTRW 36

__device__ __forceinline__ void init_bias(float d[8][4], const float* __restrict__ sb, int tg) {
#pragma unroll
    for (int nt = 0; nt < 8; nt++) {
        float2 bb = *(const float2*)&sb[8 * nt + 2 * tg];
        d[nt][0] = bb.x; d[nt][1] = bb.y; d[nt][2] = bb.x; d[nt][3] = bb.y;
    }
}

template <int NKK>
__device__ __forceinline__ void mma_layer(float d[8][4], const uint4* __restrict__ bf,
                                          const unsigned a_base, int lane) {
#pragma unroll
    for (int kk = 0; kk < NKK; kk++) {
        unsigned A0, A1, A2, A3;
        ldsm4(A0, A1, A2, A3, a_base + kk * 32);
#pragma unroll
        for (int ntp = 0; ntp < 4; ntp++) {
            uint4 b = bf[(kk * 4 + ntp) * 32 + lane];
            mma16(d[2 * ntp],     A0, A1, A2, A3, b.x, b.y);
            mma16(d[2 * ntp + 1], A0, A1, A2, A3, b.z, b.w);
        }
    }
}

// One-pass LN over 16 rows (row g via d[.][0,1], row g+8 via d[.][2,3]).
// STORE=true: pack -> tanh.f16x2 -> store half2 into hb. STORE=false: f32 tanh in regs.
template <bool STORE>
__device__ __forceinline__ void ln_tanh_frag(float d[8][4],
                                             const float* __restrict__ sg,
                                             const float* __restrict__ sbe,
                                             unsigned* __restrict__ hbu, int g, int tg) {
    float s1 = 0.f, q1 = 0.f, s2 = 0.f, q2 = 0.f;
#pragma unroll
    for (int nt = 0; nt < 8; nt++) {
        float a = d[nt][0], b = d[nt][1];
        float c = d[nt][2], e = d[nt][3];
        s1 += a + b; q1 = fmaf(a, a, q1); q1 = fmaf(b, b, q1);
        s2 += c + e; q2 = fmaf(c, c, q2); q2 = fmaf(e, e, q2);
    }
    s1 += __shfl_xor_sync(0xffffffffu, s1, 1); q1 += __shfl_xor_sync(0xffffffffu, q1, 1);
    s2 += __shfl_xor_sync(0xffffffffu, s2, 1); q2 += __shfl_xor_sync(0xffffffffu, q2, 1);
    s1 += __shfl_xor_sync(0xffffffffu, s1, 2); q1 += __shfl_xor_sync(0xffffffffu, q1, 2);
    s2 += __shfl_xor_sync(0xffffffffu, s2, 2); q2 += __shfl_xor_sync(0xffffffffu, q2, 2);
    float m1 = s1 * (1.f / 64.f), m2 = s2 * (1.f / 64.f);
    float i1 = rsqrtf(fmaf(-m1, m1, q1 * (1.f / 64.f)) + EPS);
    float i2 = rsqrtf(fmaf(-m2, m2, q2 * (1.f / 64.f)) + EPS);
#pragma unroll
    for (int nt = 0; nt < 8; nt++) {
        float2 gg = *(const float2*)&sg[8 * nt + 2 * tg];
        float2 bb = *(const float2*)&sbe[8 * nt + 2 * tg];
        float y0 = fmaf((d[nt][0] - m1) * i1, gg.x, bb.x);
        float y1 = fmaf((d[nt][1] - m1) * i1, gg.y, bb.y);
        float y2 = fmaf((d[nt][2] - m2) * i2, gg.x, bb.x);
        float y3 = fmaf((d[nt][3] - m2) * i2, gg.y, bb.y);
        if (STORE) {
            hbu[g * HSTRW + 4 * nt + tg]       = tanh2(packh2(y0, y1));
            hbu[(g + 8) * HSTRW + 4 * nt + tg] = tanh2(packh2(y2, y3));
        } else {
            d[nt][0] = tanh_fast(y0);
            d[nt][1] = tanh_fast(y1);
            d[nt][2] = tanh_fast(y2);
            d[nt][3] = tanh_fast(y3);
        }
    }
}

// smem layout (float units):
// BF0 [512] @0 | BF1 [2048] @512 | BF2 [2048] @2560
// params @4608..5247 | hb @5248: 8 warps x 16 rows x 36 words = 4608 floats
#define SMEM_FLOATS (5248 + 8 * 576)

__global__ __launch_bounds__(256, 3) void edge_mlp_tc(
    const float* __restrict__ x, const int* __restrict__ ei,
    const float* __restrict__ W0, const float* __restrict__ b0,
    const float* __restrict__ g0, const float* __restrict__ be0,
    const float* __restrict__ W1, const float* __restrict__ b1,
    const float* __restrict__ g1, const float* __restrict__ be1,
    const float* __restrict__ W2, const float* __restrict__ b2,
    const float* __restrict__ g2, const float* __restrict__ be2,
    const float* __restrict__ W3, const float* __restrict__ b3,
    float* __restrict__ out, int n_edges)
{
    extern __shared__ float sm[];
    uint4* BF0 = (uint4*)(sm);
    uint4* BF1 = (uint4*)(sm + 512);
    uint4* BF2 = (uint4*)(sm + 2560);
    float* sb0 = sm + 4608; float* sb1 = sm + 4672; float* sb2 = sm + 4736;
    float* sg0 = sm + 4800; float* sbe0 = sm + 4864;
    float* sg1 = sm + 4928; float* sbe1 = sm + 4992;
    float* sg2 = sm + 5056; float* sbe2 = sm + 5120;
    float* sw3 = sm + 5184;

    const int tid = threadIdx.x;

    // Stage B fragments as uint4 = {frag(nt=2ntp), frag(nt=2ntp+1)}
    if (tid < 128) {   // BF0: kk=0 only
        int ntp = tid >> 5, ln = tid & 31, gg = ln >> 2, tt = ln & 3;
        int k0 = 2 * tt;
        int n0 = 8 * (2 * ntp) + gg, n1 = 8 * (2 * ntp + 1) + gg;
        BF0[tid] = make_uint4(
            packh2(W0[k0 * 64 + n0],       W0[(k0 + 1) * 64 + n0]),
            packh2(W0[(k0 + 8) * 64 + n0], W0[(k0 + 9) * 64 + n0]),
            packh2(W0[k0 * 64 + n1],       W0[(k0 + 1) * 64 + n1]),
            packh2(W0[(k0 + 8) * 64 + n1], W0[(k0 + 9) * 64 + n1]));
    }
    for (int i = tid; i < 512; i += 256) {   // BF1/BF2: kk=0..3
        int kk = i >> 7, ntp = (i >> 5) & 3, ln = i & 31, gg = ln >> 2, tt = ln & 3;
        int k0 = 16 * kk + 2 * tt;
        int n0 = 8 * (2 * ntp) + gg, n1 = 8 * (2 * ntp + 1) + gg;
        BF1[i] = make_uint4(
            packh2(W1[k0 * 64 + n0],       W1[(k0 + 1) * 64 + n0]),
            packh2(W1[(k0 + 8) * 64 + n0], W1[(k0 + 9) * 64 + n0]),
            packh2(W1[k0 * 64 + n1],       W1[(k0 + 1) * 64 + n1]),
            packh2(W1[(k0 + 8) * 64 + n1], W1[(k0 + 9) * 64 + n1]));
        BF2[i] = make_uint4(
            packh2(W2[k0 * 64 + n0],       W2[(k0 + 1) * 64 + n0]),
            packh2(W2[(k0 + 8) * 64 + n0], W2[(k0 + 9) * 64 + n0]),
            packh2(W2[k0 * 64 + n1],       W2[(k0 + 1) * 64 + n1]),
            packh2(W2[(k0 + 8) * 64 + n1], W2[(k0 + 9) * 64 + n1]));
    }
    if (tid < 64) {
        sb0[tid] = b0[tid]; sb1[tid] = b1[tid]; sb2[tid] = b2[tid];
        sg0[tid] = g0[tid]; sbe0[tid] = be0[tid];
        sg1[tid] = g1[tid]; sbe1[tid] = be1[tid];
        sg2[tid] = g2[tid]; sbe2[tid] = be2[tid];
        sw3[tid] = W3[tid];
    }
    __syncthreads();
    const float b3v = b3[0];

    const int lane = tid & 31, wid = tid >> 5;
    const int g = lane >> 2, tg = lane & 3;
    unsigned* hbu = (unsigned*)(sm + 5248) + wid * (16 * HSTRW);
    const float4* x4 = (const float4*)x;

    // ldmatrix lane addressing (same mapping as proven R10 a_base0, 16 rows):
    const int lrow = lane & 15;
    const int lc4 = ((lane >> 4) & 1) * 4;
    unsigned a_base = (unsigned)__cvta_generic_to_shared(&hbu[lrow * HSTRW + lc4]);

    const int tile_stride = gridDim.x * 8 * 16;
    for (int base = (blockIdx.x * 8 + wid) * 16; base < n_edges; base += tile_stride) {
        // gather 16 edges: lanes 0-15 -> src half (words 0-3), lanes 16-31 -> dst half (words 4-7)
        int r = lane & 15;
        int e = base + r; if (e >= n_edges) e = n_edges - 1;
        int idx = (lane < 16) ? ei[e] : ei[n_edges + e];
        float4 V0 = x4[2 * idx], V1 = x4[2 * idx + 1];
        *(uint4*)&hbu[r * HSTRW + lc4] = make_uint4(
            packh2(V0.x, V0.y), packh2(V0.z, V0.w),
            packh2(V1.x, V1.y), packh2(V1.z, V1.w));
        __syncwarp();

        float d[8][4];

        // layer 0: K=16
        init_bias(d, sb0, tg);
        mma_layer<1>(d, BF0, a_base, lane);
        __syncwarp();
        ln_tanh_frag<true>(d, sg0, sbe0, hbu, g, tg);
        __syncwarp();

        // layer 1: K=64
        init_bias(d, sb1, tg);
        mma_layer<4>(d, BF1, a_base, lane);
        __syncwarp();
        ln_tanh_frag<true>(d, sg1, sbe1, hbu, g, tg);
        __syncwarp();

        // layer 2: K=64 (output stays in registers, f32 tanh)
        init_bias(d, sb2, tg);
        mma_layer<4>(d, BF2, a_base, lane);
        __syncwarp();   // hb reads done -> safe to overwrite next iteration
        ln_tanh_frag<false>(d, sg2, sbe2, hbu, g, tg);

        // layer 3: 64 -> 1, butterfly reduce over the 4-lane group
        float p1 = 0.f, p2 = 0.f;
#pragma unroll
        for (int nt = 0; nt < 8; nt++) {
            float2 w = *(const float2*)&sw3[8 * nt + 2 * tg];
            p1 = fmaf(d[nt][0], w.x, p1); p1 = fmaf(d[nt][1], w.y, p1);
            p2 = fmaf(d[nt][2], w.x, p2); p2 = fmaf(d[nt][3], w.y, p2);
        }
        p1 += __shfl_xor_sync(0xffffffffu, p1, 1); p1 += __shfl_xor_sync(0xffffffffu, p1, 2);
        p2 += __shfl_xor_sync(0xffffffffu, p2, 1); p2 += __shfl_xor_sync(0xffffffffu, p2, 2);
        if (tg == 0) {
            int e1 = base + g, e2 = base + g + 8;
            if (e1 < n_edges) out[e1] = p1 + b3v;
            if (e2 < n_edges) out[e2] = p2 + b3v;
        }
        __syncwarp();
    }
}

extern "C" void kernel_launch(void* const* d_in, const int* in_sizes, int n_in,
                              void* d_out, int out_size) {
    const float* x   = (const float*)d_in[0];
    const int*   ei  = (const int*)d_in[1];
    const float* W0 = (const float*)d_in[2];
    const float* b0 = (const float*)d_in[3];
    const float* g0 = (const float*)d_in[4];
    const float* be0 = (const float*)d_in[5];
    const float* W1 = (const float*)d_in[6];
    const float* b1 = (const float*)d_in[7];
    const float* g1 = (const float*)d_in[8];
    const float* be1 = (const float*)d_in[9];
    const float* W2 = (const float*)d_in[10];
    const float* b2 = (const float*)d_in[11];
    const float* g2 = (const float*)d_in[12];
    const float* be2 = (const float*)d_in[13];
    const float* W3 = (const float*)d_in[14];
    const float* b3 = (const float*)d_in[15];
    float* out = (float*)d_out;

    const int n_edges = in_sizes[1] / 2;
    const size_t smem_bytes = SMEM_FLOATS * sizeof(float);  // ~39.4 KB

    static bool attr_set = false;
    if (!attr_set) {
        cudaFuncSetAttribute(edge_mlp_tc, cudaFuncAttributeMaxDynamicSharedMemorySize,
                             (int)smem_bytes);
        attr_set = true;
    }

    const int threads = 256;
    const int blocks = 148 * 3;  // 3 resident blocks/SM target, grid-stride
    edge_mlp_tc<<<blocks, threads, smem_bytes>>>(x, ei,
                                                 W0, b0, g0, be0,
                                                 W1, b1, g1, be1,
                                                 W2, b2, g2, be2,
                                                 W3, b3, out, n_edges);
}